// round 5
// baseline (speedup 1.0000x reference)
#include <cuda_runtime.h>
#include <math.h>

#define D_IN  512
#define D_HID 16
#define N_OUT 40
#define MAXN  100480

// ---------------- scratch (device globals: allocation-free) ----------------
__device__ __align__(16) float g_deg [MAXN];          // deg, then dinv in-place
__device__ __align__(16) float g_h1  [MAXN * D_HID];  // x @ W1
__device__ __align__(16) float g_out1[MAXN * D_HID];  // layer-1 output
__device__ __align__(16) float g_agg2[MAXN * D_HID];  // A_norm @ out1

// ---------------- tiny helpers ----------------
__device__ __forceinline__ void red4(float* p, float a, float b, float c, float d) {
    asm volatile("red.global.add.v4.f32 [%0], {%1,%2,%3,%4};"
                 :: "l"(p), "f"(a), "f"(b), "f"(c), "f"(d) : "memory");
}

// ---------------- degree / dinv ----------------
__global__ void k_init_deg(int n) {
    int i = blockIdx.x * blockDim.x + threadIdx.x;
    if (i < n) g_deg[i] = 1.0f;               // self-loop weight
}

__global__ void k_deg(const int* __restrict__ ei,
                      const float* __restrict__ attr, int E) {
    int e = blockIdx.x * blockDim.x + threadIdx.x;
    if (e < E) {
        int d = ei[E + e];                    // dst row (int32!)
        atomicAdd(&g_deg[d], attr[e]);
    }
}

__global__ void k_dinv(int n) {
    int i = blockIdx.x * blockDim.x + threadIdx.x;
    if (i < n) {
        float d = g_deg[i];
        g_deg[i] = (d > 0.0f) ? rsqrtf(d) : 0.0f;
    }
}

// ---------------- GEMM1: h1 = x @ W1  (n x 512) @ (512 x 16) ----------------
#define GROWS 256
#define GKC   32
__global__ void k_gemm1(const float* __restrict__ x,
                        const float* __restrict__ W, int n) {
    __shared__ __align__(16) float Xs[GROWS][GKC + 4];  // 144B row: 16B-multiple
    __shared__ __align__(16) float Ws[D_HID][GKC + 4];
    int t = threadIdx.x;                       // 256 threads
    int rowBase = blockIdx.x * GROWS;
    int fg = t & 3;                            // 4 feature groups (f = fg*4..+3)
    int rg = t >> 2;                           // 64 row groups (r = rg*4..+3)
    int lr = t >> 3, lv = t & 7;               // loader mapping

    float acc[4][4];
#pragma unroll
    for (int i = 0; i < 4; i++)
#pragma unroll
        for (int j = 0; j < 4; j++) acc[i][j] = 0.0f;

    for (int kc = 0; kc < D_IN; kc += GKC) {
#pragma unroll
        for (int i = 0; i < 8; i++) {
            int r = lr + 32 * i;
            int grow = rowBase + r;
            float4 v = make_float4(0.f, 0.f, 0.f, 0.f);
            if (grow < n)
                v = *(const float4*)&x[(size_t)grow * D_IN + kc + lv * 4];
            *(float4*)&Xs[r][lv * 4] = v;
        }
        if (t < 128) {
            int f = t >> 3, kk = (t & 7) * 4;
#pragma unroll
            for (int j = 0; j < 4; j++)
                Ws[f][kk + j] = W[(size_t)(kc + kk + j) * D_HID + f];
        }
        __syncthreads();
#pragma unroll
        for (int kk = 0; kk < GKC; kk += 4) {
            float4 xv[4], wv[4];
#pragma unroll
            for (int j = 0; j < 4; j++) xv[j] = *(const float4*)&Xs[rg * 4 + j][kk];
#pragma unroll
            for (int j = 0; j < 4; j++) wv[j] = *(const float4*)&Ws[fg * 4 + j][kk];
#pragma unroll
            for (int i = 0; i < 4; i++)
#pragma unroll
                for (int j = 0; j < 4; j++)
                    acc[i][j] += xv[i].x * wv[j].x + xv[i].y * wv[j].y
                               + xv[i].z * wv[j].z + xv[i].w * wv[j].w;
        }
        __syncthreads();
    }
#pragma unroll
    for (int i = 0; i < 4; i++) {
        int row = rowBase + rg * 4 + i;
        if (row < n) {
            float4 o = make_float4(acc[i][0], acc[i][1], acc[i][2], acc[i][3]);
            *(float4*)&g_h1[(size_t)row * D_HID + fg * 4] = o;
        }
    }
}

// ---------------- node-wise inits (bias + self-loop contribution) ----------
__global__ void k_node1(const float* __restrict__ b1, int n) {
    int idx = blockIdx.x * blockDim.x + threadIdx.x;
    if (idx >= n * D_HID) return;
    int i = idx >> 4, f = idx & 15;
    float dv = g_deg[i];                       // dinv now
    g_out1[idx] = b1[f] + dv * dv * g_h1[idx];
}

__global__ void k_node2(int n) {
    int idx = blockIdx.x * blockDim.x + threadIdx.x;
    if (idx >= n * D_HID) return;
    int i = idx >> 4;
    float dv = g_deg[i];
    g_agg2[idx] = dv * dv * g_out1[idx];
}

// ---------------- edge scatter: hout[dst] += norm(e) * hin[src] ------------
template <int PHASE>
__global__ void k_scatter(const int* __restrict__ ei,
                          const float* __restrict__ attr, int E) {
    int e = blockIdx.x * blockDim.x + threadIdx.x;
    if (e >= E) return;
    int s = ei[e];
    int d = ei[E + e];
    float nrm = g_deg[s] * attr[e] * g_deg[d];     // dinv[src]*w*dinv[dst]
    const float4* hin = (PHASE == 0) ? (const float4*)g_h1 : (const float4*)g_out1;
    float* hout       = (PHASE == 0) ? g_out1 : g_agg2;
    const float4* hs = hin + (size_t)s * 4;
    float* p = hout + (size_t)d * D_HID;
    float4 a;
    a = hs[0]; red4(p + 0,  nrm * a.x, nrm * a.y, nrm * a.z, nrm * a.w);
    a = hs[1]; red4(p + 4,  nrm * a.x, nrm * a.y, nrm * a.z, nrm * a.w);
    a = hs[2]; red4(p + 8,  nrm * a.x, nrm * a.y, nrm * a.z, nrm * a.w);
    a = hs[3]; red4(p + 12, nrm * a.x, nrm * a.y, nrm * a.z, nrm * a.w);
}

// ---------------- epilogue: logits = agg2 @ W2 + b2 ; log_softmax ----------
__global__ void k_final(const float* __restrict__ W2,
                        const float* __restrict__ b2,
                        float* __restrict__ out, int n) {
    __shared__ __align__(16) float sW[D_HID * N_OUT];
    __shared__ float sb[N_OUT];
    int t = threadIdx.x;
    for (int i = t; i < D_HID * N_OUT; i += blockDim.x) sW[i] = W2[i];
    if (t < N_OUT) sb[t] = b2[t];
    __syncthreads();

    int warp = t >> 5, lane = t & 31;
    int node = blockIdx.x * (blockDim.x >> 5) + warp;
    if (node >= n) return;

    float a = (lane < D_HID) ? g_agg2[(size_t)node * D_HID + lane] : 0.0f;
    int f0 = lane;
    int f1c = (lane < 8) ? lane + 32 : 0;      // clamped index for safe smem read
    float z0 = sb[f0];
    float acc1 = 0.0f;
#pragma unroll
    for (int k = 0; k < D_HID; k++) {
        float ak = __shfl_sync(0xffffffffu, a, k);
        z0   += ak * sW[k * N_OUT + f0];
        acc1 += ak * sW[k * N_OUT + f1c];
    }
    float z1 = (lane < 8) ? (sb[lane + 32] + acc1) : -INFINITY;

    float m = fmaxf(z0, z1);
#pragma unroll
    for (int o = 16; o > 0; o >>= 1) m = fmaxf(m, __shfl_xor_sync(0xffffffffu, m, o));
    float s = expf(z0 - m) + ((lane < 8) ? expf(z1 - m) : 0.0f);
#pragma unroll
    for (int o = 16; o > 0; o >>= 1) s += __shfl_xor_sync(0xffffffffu, s, o);
    float ls = m + logf(s);

    out[(size_t)node * N_OUT + f0] = z0 - ls;
    if (lane < 8) out[(size_t)node * N_OUT + lane + 32] = z1 - ls;
}

// ---------------- launch ----------------
extern "C" void kernel_launch(void* const* d_in, const int* in_sizes, int n_in,
                              void* d_out, int out_size) {
    // Bind inputs BY ELEMENT COUNT — immune to metadata ordering.
    // x: n*512 (largest), edge_index: 2E int32, edge_attr: E,
    // W1: 8192, W2: 640, b2: 40, b1: 16.
    const float* x    = nullptr;
    const int*   ei   = nullptr;
    const float* attr = nullptr;
    const float* W1   = nullptr;
    const float* b1   = nullptr;
    const float* W2   = nullptr;
    const float* b2   = nullptr;

    long long szmax = -1; int ix = -1;
    for (int i = 0; i < n_in; i++)
        if ((long long)in_sizes[i] > szmax) { szmax = in_sizes[i]; ix = i; }
    x = (const float*)d_in[ix];

    long long sz2 = -1; int ie = -1;
    for (int i = 0; i < n_in; i++)
        if (i != ix && (long long)in_sizes[i] > sz2) { sz2 = in_sizes[i]; ie = i; }
    ei = (const int*)d_in[ie];              // int32 edge_index [2, E]
    int E = (int)(sz2 / 2);

    for (int i = 0; i < n_in; i++) {
        if (i == ix || i == ie) continue;
        int s = in_sizes[i];
        if      (s == E)              attr = (const float*)d_in[i];
        else if (s == D_IN * D_HID)   W1   = (const float*)d_in[i];
        else if (s == D_HID)          b1   = (const float*)d_in[i];
        else if (s == D_HID * N_OUT)  W2   = (const float*)d_in[i];
        else if (s == N_OUT)          b2   = (const float*)d_in[i];
    }

    float* out = (float*)d_out;
    int n = (int)(szmax / D_IN);     // 100000

    int tb = 256;
    int nb_nodes = (n + tb - 1) / tb;
    int nb_edges = (E + tb - 1) / tb;
    int nb_nf    = (n * D_HID + tb - 1) / tb;

    k_init_deg<<<nb_nodes, tb>>>(n);
    k_deg<<<nb_edges, tb>>>(ei, attr, E);
    k_dinv<<<nb_nodes, tb>>>(n);

    k_gemm1<<<(n + GROWS - 1) / GROWS, 256>>>(x, W1, n);

    k_node1<<<nb_nf, tb>>>(b1, n);
    k_scatter<0><<<nb_edges, tb>>>(ei, attr, E);

    k_node2<<<nb_nf, tb>>>(n);
    k_scatter<1><<<nb_edges, tb>>>(ei, attr, E);

    k_final<<<(n + 7) / 8, 256>>>(W2, b2, out, n);
}

// round 10
// speedup vs baseline: 1.1580x; 1.1580x over previous
#include <cuda_runtime.h>
#include <cstdint>
#include <math.h>

#define D_IN  512
#define D_HID 16
#define N_OUT 40
#define MAXN  100480
#define MAXE  3276800

// ---------------- scratch (device globals: allocation-free) ----------------
__device__ __align__(16) float g_deg [MAXN];          // deg, then dinv in-place
__device__ __align__(16) float g_norm[MAXE];          // per-edge norm
__device__ __align__(16) float g_h1  [MAXN * D_HID];  // x @ W1
__device__ __align__(16) float g_out1[MAXN * D_HID];  // layer-1 output
__device__ __align__(16) float g_agg2[MAXN * D_HID];  // A_norm @ out1

// ---------------- tiny helpers ----------------
__device__ __forceinline__ void red4(float* p, float a, float b, float c, float d) {
    asm volatile("red.global.add.v4.f32 [%0], {%1,%2,%3,%4};"
                 :: "l"(p), "f"(a), "f"(b), "f"(c), "f"(d) : "memory");
}
__device__ __forceinline__ void cpa16(uint32_t dst, const void* src) {
    asm volatile("cp.async.cg.shared.global [%0], [%1], 16;" :: "r"(dst), "l"(src));
}
__device__ __forceinline__ void cpa_commit() { asm volatile("cp.async.commit_group;"); }
template <int N> __device__ __forceinline__ void cpa_wait() {
    asm volatile("cp.async.wait_group %0;" :: "n"(N));
}

// ---------------- degree / dinv / norm ----------------
__global__ void k_init_deg(int n) {
    int i = blockIdx.x * blockDim.x + threadIdx.x;
    if (i < n) g_deg[i] = 1.0f;               // self-loop weight
}

__global__ void k_deg(const int* __restrict__ ei,
                      const float* __restrict__ attr, int E) {
    int e = blockIdx.x * blockDim.x + threadIdx.x;
    if (e < E) atomicAdd(&g_deg[ei[E + e]], attr[e]);
}

__global__ void k_dinv(int n) {
    int i = blockIdx.x * blockDim.x + threadIdx.x;
    if (i < n) {
        float d = g_deg[i];
        g_deg[i] = (d > 0.0f) ? rsqrtf(d) : 0.0f;
    }
}

__global__ void k_norm(const int* __restrict__ ei,
                       const float* __restrict__ attr, int E) {
    int e = blockIdx.x * blockDim.x + threadIdx.x;
    if (e < E) g_norm[e] = g_deg[ei[e]] * attr[e] * g_deg[ei[E + e]];
}

// ---------------- GEMM1: h1 = x @ W1  (n x 512) @ (512 x 16) ----------------
// 256 threads; thread = 4 rows x 4 feats; rows strided by 64 for
// conflict-free LDS (20-word row stride -> 8 distinct banks across a warp).
// cp.async double-buffered k-chunks of 16.
#define GROWS 256
#define GKC   16
#define XSTR  (GKC + 4)
__global__ void k_gemm1(const float* __restrict__ x,
                        const float* __restrict__ W, int n) {
    __shared__ __align__(16) float Xs[2][GROWS][XSTR];
    __shared__ __align__(16) float Ws[2][GKC][16];   // [k][f], no transpose
    int t = threadIdx.x;
    int rowBase = blockIdx.x * GROWS;
    int fg = t & 3;            // feature group: f = fg*4 .. +3
    int rg = t >> 2;           // 0..63 ; rows = rg + 64*i

    float acc[4][4];
#pragma unroll
    for (int i = 0; i < 4; i++)
#pragma unroll
        for (int j = 0; j < 4; j++) acc[i][j] = 0.0f;

    // chunk loader: Xs tile (256x16) as 1024 float4 (4/thread), Ws (16x16) as 64 float4
    auto load_chunk = [&](int kc, int buf) {
#pragma unroll
        for (int i = 0; i < 4; i++) {
            int f4  = t + 256 * i;
            int row = f4 >> 2, q = f4 & 3;
            int grow = rowBase + row;
            if (grow < n) {
                uint32_t dst = (uint32_t)__cvta_generic_to_shared(&Xs[buf][row][q * 4]);
                cpa16(dst, &x[(size_t)grow * D_IN + kc + q * 4]);
            }
        }
        if (t < 64) {
            int k = t >> 2, q = t & 3;
            uint32_t dst = (uint32_t)__cvta_generic_to_shared(&Ws[buf][k][q * 4]);
            cpa16(dst, &W[(size_t)(kc + k) * D_HID + q * 4]);
        }
    };

    load_chunk(0, 0);
    cpa_commit();

    const int nchunks = D_IN / GKC;   // 32
    for (int c = 0; c < nchunks; c++) {
        int cur = c & 1;
        if (c + 1 < nchunks) {
            load_chunk((c + 1) * GKC, cur ^ 1);
            cpa_commit();
            cpa_wait<1>();
        } else {
            cpa_wait<0>();
        }
        __syncthreads();
#pragma unroll
        for (int kk = 0; kk < GKC; kk += 4) {
            float4 xv[4], wv[4];
#pragma unroll
            for (int i = 0; i < 4; i++)
                xv[i] = *(const float4*)&Xs[cur][rg + 64 * i][kk];
#pragma unroll
            for (int q = 0; q < 4; q++)
                wv[q] = *(const float4*)&Ws[cur][kk + q][fg * 4];
#pragma unroll
            for (int i = 0; i < 4; i++) {
                acc[i][0] += xv[i].x * wv[0].x + xv[i].y * wv[1].x
                           + xv[i].z * wv[2].x + xv[i].w * wv[3].x;
                acc[i][1] += xv[i].x * wv[0].y + xv[i].y * wv[1].y
                           + xv[i].z * wv[2].y + xv[i].w * wv[3].y;
                acc[i][2] += xv[i].x * wv[0].z + xv[i].y * wv[1].z
                           + xv[i].z * wv[2].z + xv[i].w * wv[3].z;
                acc[i][3] += xv[i].x * wv[0].w + xv[i].y * wv[1].w
                           + xv[i].z * wv[2].w + xv[i].w * wv[3].w;
            }
        }
        __syncthreads();
    }
#pragma unroll
    for (int i = 0; i < 4; i++) {
        int row = rowBase + rg + 64 * i;
        if (row < n)
            *(float4*)&g_h1[(size_t)row * D_HID + fg * 4] =
                make_float4(acc[i][0], acc[i][1], acc[i][2], acc[i][3]);
    }
}

// ---------------- node-wise inits (bias + self-loop contribution) ----------
__global__ void k_node1(const float* __restrict__ b1, int n) {
    int idx = blockIdx.x * blockDim.x + threadIdx.x;
    if (idx >= n * D_HID) return;
    int i = idx >> 4, f = idx & 15;
    float dv = g_deg[i];                       // dinv now
    g_out1[idx] = b1[f] + dv * dv * g_h1[idx];
}

__global__ void k_node2(int n) {
    int idx = blockIdx.x * blockDim.x + threadIdx.x;
    if (idx >= n * D_HID) return;
    int i = idx >> 4;
    float dv = g_deg[i];
    g_agg2[idx] = dv * dv * g_out1[idx];
}

// ---------------- edge scatter: hout[dst] += norm(e) * hin[src] ------------
template <int PHASE>
__global__ void k_scatter(const int* __restrict__ ei, int E) {
    int e = blockIdx.x * blockDim.x + threadIdx.x;
    if (e >= E) return;
    int s = ei[e];
    int d = ei[E + e];
    float nrm = g_norm[e];
    const float4* hin = (PHASE == 0) ? (const float4*)g_h1 : (const float4*)g_out1;
    float* hout       = (PHASE == 0) ? g_out1 : g_agg2;
    const float4* hs = hin + (size_t)s * 4;
    float* p = hout + (size_t)d * D_HID;
    float4 a;
    a = hs[0]; red4(p + 0,  nrm * a.x, nrm * a.y, nrm * a.z, nrm * a.w);
    a = hs[1]; red4(p + 4,  nrm * a.x, nrm * a.y, nrm * a.z, nrm * a.w);
    a = hs[2]; red4(p + 8,  nrm * a.x, nrm * a.y, nrm * a.z, nrm * a.w);
    a = hs[3]; red4(p + 12, nrm * a.x, nrm * a.y, nrm * a.z, nrm * a.w);
}

// ---------------- epilogue: logits = agg2 @ W2 + b2 ; log_softmax ----------
__global__ void k_final(const float* __restrict__ W2,
                        const float* __restrict__ b2,
                        float* __restrict__ out, int n) {
    __shared__ __align__(16) float sW[D_HID * N_OUT];
    __shared__ float sb[N_OUT];
    int t = threadIdx.x;
    for (int i = t; i < D_HID * N_OUT; i += blockDim.x) sW[i] = W2[i];
    if (t < N_OUT) sb[t] = b2[t];
    __syncthreads();

    int warp = t >> 5, lane = t & 31;
    int node = blockIdx.x * (blockDim.x >> 5) + warp;
    if (node >= n) return;

    float a = (lane < D_HID) ? g_agg2[(size_t)node * D_HID + lane] : 0.0f;
    int f0 = lane;
    int f1c = (lane < 8) ? lane + 32 : 0;
    float z0 = sb[f0];
    float acc1 = 0.0f;
#pragma unroll
    for (int k = 0; k < D_HID; k++) {
        float ak = __shfl_sync(0xffffffffu, a, k);
        z0   += ak * sW[k * N_OUT + f0];
        acc1 += ak * sW[k * N_OUT + f1c];
    }
    float z1 = (lane < 8) ? (sb[lane + 32] + acc1) : -INFINITY;

    float m = fmaxf(z0, z1);
#pragma unroll
    for (int o = 16; o > 0; o >>= 1) m = fmaxf(m, __shfl_xor_sync(0xffffffffu, m, o));
    float s = expf(z0 - m) + ((lane < 8) ? expf(z1 - m) : 0.0f);
#pragma unroll
    for (int o = 16; o > 0; o >>= 1) s += __shfl_xor_sync(0xffffffffu, s, o);
    float ls = m + logf(s);

    out[(size_t)node * N_OUT + f0] = z0 - ls;
    if (lane < 8) out[(size_t)node * N_OUT + lane + 32] = z1 - ls;
}

// ---------------- launch ----------------
extern "C" void kernel_launch(void* const* d_in, const int* in_sizes, int n_in,
                              void* d_out, int out_size) {
    // Bind inputs BY ELEMENT COUNT — immune to metadata ordering.
    const float* x    = nullptr;
    const int*   ei   = nullptr;
    const float* attr = nullptr;
    const float* W1   = nullptr;
    const float* b1   = nullptr;
    const float* W2   = nullptr;
    const float* b2   = nullptr;

    long long szmax = -1; int ix = -1;
    for (int i = 0; i < n_in; i++)
        if ((long long)in_sizes[i] > szmax) { szmax = in_sizes[i]; ix = i; }
    x = (const float*)d_in[ix];

    long long sz2 = -1; int ie = -1;
    for (int i = 0; i < n_in; i++)
        if (i != ix && (long long)in_sizes[i] > sz2) { sz2 = in_sizes[i]; ie = i; }
    ei = (const int*)d_in[ie];              // int32 edge_index [2, E]
    int E = (int)(sz2 / 2);

    for (int i = 0; i < n_in; i++) {
        if (i == ix || i == ie) continue;
        int s = in_sizes[i];
        if      (s == E)              attr = (const float*)d_in[i];
        else if (s == D_IN * D_HID)   W1   = (const float*)d_in[i];
        else if (s == D_HID)          b1   = (const float*)d_in[i];
        else if (s == D_HID * N_OUT)  W2   = (const float*)d_in[i];
        else if (s == N_OUT)          b2   = (const float*)d_in[i];
    }

    float* out = (float*)d_out;
    int n = (int)(szmax / D_IN);     // 100000

    int tb = 256;
    int nb_nodes = (n + tb - 1) / tb;
    int nb_edges = (E + tb - 1) / tb;
    int nb_nf    = (n * D_HID + tb - 1) / tb;

    k_init_deg<<<nb_nodes, tb>>>(n);
    k_deg<<<nb_edges, tb>>>(ei, attr, E);
    k_dinv<<<nb_nodes, tb>>>(n);
    k_norm<<<nb_edges, tb>>>(ei, attr, E);

    k_gemm1<<<(n + GROWS - 1) / GROWS, 256>>>(x, W1, n);

    k_node1<<<nb_nf, tb>>>(b1, n);
    k_scatter<0><<<nb_edges, tb>>>(ei, E);

    k_node2<<<nb_nf, tb>>>(n);
    k_scatter<1><<<nb_edges, tb>>>(ei, E);

    k_final<<<(n + 7) / 8, 256>>>(W2, b2, out, n);
}